// round 7
// baseline (speedup 1.0000x reference)
#include <cuda_runtime.h>
#include <cstdint>

#define Tn   4096
#define Bn   64
#define Hn   256
#define INC  16
#define OUTC 20

typedef unsigned long long ull;

// ---------------- scratch (device globals; no allocations) ---------------
__device__ float g_h1[(size_t)Tn * Bn * Hn];        // 256 MB
__device__ float g_h2[(size_t)Tn * Bn * Hn];        // 256 MB
__device__ float g_xw[(size_t)Tn * Bn * 4 * Hn];    // 1 GB (reused per layer)

// ---------------- helpers ------------------------------------------------
__device__ __forceinline__ ull fma2(ull a, ull b, ull c) {
    ull d; asm("fma.rn.f32x2 %0, %1, %2, %3;" : "=l"(d) : "l"(a), "l"(b), "l"(c));
    return d;
}
__device__ __forceinline__ ull add2(ull a, ull b) {
    ull d; asm("add.rn.f32x2 %0, %1, %2;" : "=l"(d) : "l"(a), "l"(b));
    return d;
}
__device__ __forceinline__ ull pk2(float lo, float hi) {
    ull r; asm("mov.b64 %0, {%1, %2};" : "=l"(r) : "f"(lo), "f"(hi)); return r;
}
__device__ __forceinline__ ull dup2(float v) {
    ull r; asm("mov.b64 %0, {%1, %1};" : "=l"(r) : "f"(v)); return r;
}
__device__ __forceinline__ float2 unpk(ull v) {
    float2 f; asm("mov.b64 {%0, %1}, %2;" : "=f"(f.x), "=f"(f.y) : "l"(v));
    return f;
}
__device__ __forceinline__ uint32_t s2u(const void* p) {
    uint32_t a;
    asm("{ .reg .u64 t; cvta.to.shared.u64 t, %1; cvt.u32.u64 %0, t; }"
        : "=r"(a) : "l"(p));
    return a;
}
__device__ __forceinline__ uint32_t ctarank() {
    uint32_t r; asm("mov.u32 %0, %%cluster_ctarank;" : "=r"(r)); return r;
}
__device__ __forceinline__ void cluster_sync_() {
    asm volatile("barrier.cluster.arrive.aligned;" ::: "memory");
    asm volatile("barrier.cluster.wait.aligned;" ::: "memory");
}
__device__ __forceinline__ void st_async64(uint32_t raddr, uint32_t rmbar,
                                           ull v) {
    asm volatile(
        "st.async.shared::cluster.mbarrier::complete_tx::bytes.b64 [%0], %1, [%2];"
        :: "r"(raddr), "l"(v), "r"(rmbar) : "memory");
}
__device__ __forceinline__ void mbar_init(uint32_t mbar, uint32_t cnt) {
    asm volatile("mbarrier.init.shared.b64 [%0], %1;" :: "r"(mbar), "r"(cnt)
                 : "memory");
}
__device__ __forceinline__ void mbar_expect(uint32_t mbar, uint32_t bytes) {
    asm volatile("mbarrier.arrive.expect_tx.shared.b64 _, [%0], %1;"
                 :: "r"(mbar), "r"(bytes) : "memory");
}
__device__ __forceinline__ void mbar_wait(uint32_t mbar, int phase) {
    asm volatile(
        "{\n\t.reg .pred P;\n"
        "W%=:\n\t"
        "mbarrier.try_wait.parity.acquire.cta.shared::cta.b64 P, [%0], %1, 0x989680;\n\t"
        "@P bra D%=;\n\t"
        "bra W%=;\n"
        "D%=:\n\t}"
        :: "r"(mbar), "r"(phase) : "memory");
}
__device__ __forceinline__ float sigm(float x) {
    return __fdividef(1.f, 1.f + __expf(-x));
}
__device__ __forceinline__ float tanh_fast(float x) {
    float ax = fabsf(x);
    float e  = __expf(ax + ax);
    float t  = 1.f - __fdividef(2.f, e + 1.f);
    return copysignf(t, x);
}

// =========================== recurrent kernel ============================
// grid 128, cluster 8, 256 threads. Cluster cid owns batches [cid*4,+4);
// CTA rank r owns hidden units [r*32,+32); local gate cols c = q*32 + j.
// Dynamic SMEM bytes:
//   buf    [3][4][256] f32 @     0 (12288 B)  h triple buffer
//   mbar   [3] u64         @ 12288 (24 B, pad to 32)
//   part   [8][4][128] ull @ 12320 (32768 B)  k-split partials
//   hstage [4][32]  f32    @ 45088 (512 B)
#define RC_SMEM 45600

__global__ void __launch_bounds__(256, 1) __cluster_dims__(8, 1, 1)
lstm_recur(const float* __restrict__ Whh, int layer)
{
    extern __shared__ __align__(16) char smraw[];
    float* buf    = (float*)smraw;
    ull*   part   = (ull*)(smraw + 12320);
    float* hstage = (float*)(smraw + 45088);
    float* hout   = layer ? g_h2 : g_h1;
    const float* xw = g_xw;

    const int tid  = threadIdx.x;
    const int rank = (int)ctarank();
    const int cid  = blockIdx.x >> 3;
    const int b0   = cid * 4;
    const int j0   = rank * 32;
    const int cq   = tid & 31, ks = tid >> 5;
    const int c0   = cq * 4,   k0 = ks * 32;

    // ---- weights: 4 cols x 32 k, packed over k pairs (registers) ----
    ull w[4][16];
    #pragma unroll
    for (int ci = 0; ci < 4; ++ci) {
        int c  = c0 + ci;
        int gr = ((c >> 5) << 8) + j0 + (c & 31);
        const float4* wp = (const float4*)(Whh + (size_t)gr * Hn + k0);
        #pragma unroll
        for (int q = 0; q < 8; ++q) {
            float4 v = wp[q];
            w[ci][2*q]   = pk2(v.x, v.y);
            w[ci][2*q+1] = pk2(v.z, v.w);
        }
    }

    const uint32_t sbase = s2u(smraw);
    const uint32_t mbar0 = sbase + 12288;

    for (int i = tid; i < 1024; i += 256) buf[i] = 0.f;   // h(0)=0 in buf 0
    if (tid == 0) {
        mbar_init(mbar0,      1);
        mbar_init(mbar0 + 8,  1);
        mbar_init(mbar0 + 16, 1);
    }
    __syncthreads();
    cluster_sync_();          // mbars + buf0 visible cluster-wide

    uint32_t rbase[8];
    #pragma unroll
    for (int r = 0; r < 8; ++r)
        asm("mapa.shared::cluster.u32 %0, %1, %2;"
            : "=r"(rbase[r]) : "r"(sbase), "r"(r));

    // fan-out constants: thread sends pair p to ranks (tid>>6) and (tid>>6)+4
    const int fp   = tid & 63;                 // pair id: b = fp>>4, jp = fp&15
    const int fr   = tid >> 6;
    const uint32_t foff_base =
        (uint32_t)((fp >> 4) * 256 + j0 + 2 * (fp & 15)) * 4u;

    float creg = 0.f;
    int p0 = 0, p1 = 0, p2 = 0;
    int cur = 0;

    for (int t = 0; t < Tn; ++t) {
        const int nxt = (cur == 2) ? 0 : cur + 1;

        // ---- xw prefetch (before wait; DRAM latency hidden) ----
        float x0, x1, x2, x3;
        if (tid < 128) {
            const float* xp = xw + ((size_t)t * Bn + b0 + ks) * 1024 + j0 + cq;
            x0 = xp[0]; x1 = xp[256]; x2 = xp[512]; x3 = xp[768];
        }

        // ---- wait for h(t) ----
        if (t > 0) {
            int ph = (cur == 0) ? p0 : ((cur == 1) ? p1 : p2);
            mbar_wait(mbar0 + cur * 8, ph);
            if (cur == 0) p0 ^= 1; else if (cur == 1) p1 ^= 1; else p2 ^= 1;
        }
        if (tid == 0 && t < Tn - 1) mbar_expect(mbar0 + nxt * 8, 4096);

        // ---- gate partials: 4 cols x 4 batches x 32 k (k-pair packed) ----
        ull acc[4][4];
        #pragma unroll
        for (int ci = 0; ci < 4; ++ci)
            #pragma unroll
            for (int b = 0; b < 4; ++b) acc[ci][b] = 0;
        {
            const ull* hb = (const ull*)buf + cur * 512 + (k0 >> 1);
            #pragma unroll
            for (int b = 0; b < 4; ++b) {
                const ull* hp = hb + b * 128;
                #pragma unroll
                for (int q = 0; q < 16; ++q) {
                    ull h2 = hp[q];
                    acc[0][b] = fma2(h2, w[0][q], acc[0][b]);
                    acc[1][b] = fma2(h2, w[1][q], acc[1][b]);
                    acc[2][b] = fma2(h2, w[2][q], acc[2][b]);
                    acc[3][b] = fma2(h2, w[3][q], acc[3][b]);
                }
            }
        }
        {
            ull* pp = part + (size_t)(ks * 4) * 128 + c0;
            #pragma unroll
            for (int b = 0; b < 4; ++b) {
                ulonglong2 v0; v0.x = acc[0][b]; v0.y = acc[1][b];
                ulonglong2 v1; v1.x = acc[2][b]; v1.y = acc[3][b];
                *(ulonglong2*)(pp + b * 128)     = v0;
                *(ulonglong2*)(pp + b * 128 + 2) = v1;
            }
        }
        __syncthreads();

        // ---- merged reduce + activate (128 threads) ----
        if (tid < 128) {
            const int b = ks, j = cq;          // b = tid>>5 (0..3), j = tid&31
            const ull* pb = part + b * 128 + j;
            ull s0 = pb[0], s1 = pb[32], s2 = pb[64], s3 = pb[96];
            #pragma unroll
            for (int q = 1; q < 8; ++q) {
                const ull* pq = pb + q * 512;
                s0 = add2(s0, pq[0]);
                s1 = add2(s1, pq[32]);
                s2 = add2(s2, pq[64]);
                s3 = add2(s3, pq[96]);
            }
            float2 u0 = unpk(s0), u1 = unpk(s1), u2 = unpk(s2), u3 = unpk(s3);
            float ii = sigm(u0.x + u0.y + x0);
            float ff = sigm(u1.x + u1.y + x1);
            float gg = tanh_fast(u2.x + u2.y + x2);
            float oo = sigm(u3.x + u3.y + x3);
            creg = ff * creg + ii * gg;
            float h = oo * tanh_fast(creg);
            hout[((size_t)t * Bn + b0 + b) * Hn + j0 + j] = h;
            hstage[b * 32 + j] = h;
        }
        __syncthreads();

        // ---- fan-out: 512 b64 sends spread over all 256 threads ----
        if (t < Tn - 1) {
            ull hv = ((const ull*)hstage)[fp];
            uint32_t off  = (uint32_t)(nxt * 4096) + foff_base;
            uint32_t moff = 12288u + (uint32_t)nxt * 8u;
            st_async64(rbase[fr]     + off, rbase[fr]     + moff, hv);
            st_async64(rbase[fr + 4] + off, rbase[fr + 4] + moff, hv);
        }
        cur = nxt;
    }
    cluster_sync_();
}

// =========================== pre1: xw = x*Wih0^T + b =====================
__global__ void __launch_bounds__(256, 2)
pre1_gemm(const float* __restrict__ x, const float* __restrict__ Wih,
          const float* __restrict__ bih, const float* __restrict__ bhh)
{
    __shared__ float xs[64 * 16];
    const int tid = threadIdx.x;
    const int t0  = blockIdx.x * 16;
    const int b0  = blockIdx.y * 4;
    const int g0  = tid * 4;

    ull w[16][2];
    {
        const float4* w0 = (const float4*)(Wih + (size_t)(g0 + 0) * INC);
        const float4* w1 = (const float4*)(Wih + (size_t)(g0 + 1) * INC);
        const float4* w2 = (const float4*)(Wih + (size_t)(g0 + 2) * INC);
        const float4* w3 = (const float4*)(Wih + (size_t)(g0 + 3) * INC);
        #pragma unroll
        for (int dq = 0; dq < 4; ++dq) {
            float4 A = w0[dq], B = w1[dq], C = w2[dq], D = w3[dq];
            w[dq*4+0][0] = pk2(A.x, B.x);  w[dq*4+0][1] = pk2(C.x, D.x);
            w[dq*4+1][0] = pk2(A.y, B.y);  w[dq*4+1][1] = pk2(C.y, D.y);
            w[dq*4+2][0] = pk2(A.z, B.z);  w[dq*4+2][1] = pk2(C.z, D.z);
            w[dq*4+3][0] = pk2(A.w, B.w);  w[dq*4+3][1] = pk2(C.w, D.w);
        }
    }
    ull bp0 = pk2(bih[g0+0] + bhh[g0+0], bih[g0+1] + bhh[g0+1]);
    ull bp1 = pk2(bih[g0+2] + bhh[g0+2], bih[g0+3] + bhh[g0+3]);

    for (int idx = tid; idx < 1024; idx += 256) {
        int row = idx >> 4, d = idx & 15;
        int tt = row >> 2, bb = row & 3;
        xs[idx] = x[(size_t)(b0 + bb) * INC * Tn + (size_t)d * Tn + t0 + tt];
    }
    __syncthreads();

    for (int row = 0; row < 64; ++row) {
        ull a0 = bp0, a1 = bp1;
        const float* xr = xs + row * 16;
        #pragma unroll
        for (int d = 0; d < 16; ++d) {
            ull xd = dup2(xr[d]);
            a0 = fma2(xd, w[d][0], a0);
            a1 = fma2(xd, w[d][1], a1);
        }
        int tt = row >> 2, bb = row & 3;
        size_t m = (size_t)(t0 + tt) * Bn + b0 + bb;
        float2 u0 = unpk(a0), u1 = unpk(a1);
        *(float4*)(g_xw + m * 1024 + g0) = make_float4(u0.x, u0.y, u1.x, u1.y);
    }
}

// =========================== pre2: xw = h1*Wih1^T + b ====================
__global__ void __launch_bounds__(256, 2)
pre2_gemm(const float* __restrict__ Wih,
          const float* __restrict__ bih, const float* __restrict__ bhh)
{
    __shared__ __align__(16) float2 As2[16 * 128];
    __shared__ __align__(16) float  Bs[16 * 128];
    const int tid  = threadIdx.x;
    const int mblk = blockIdx.x * 128;
    const int gblk = blockIdx.y * 128;
    const int tm = tid >> 4, tn = tid & 15;
    const int m0 = tm * 8,   n0 = tn * 8;

    ull acc[8][4];
    {
        ull bp[4];
        #pragma unroll
        for (int p = 0; p < 4; ++p) {
            int g = gblk + n0 + 2 * p;
            bp[p] = pk2(bih[g] + bhh[g], bih[g+1] + bhh[g+1]);
        }
        #pragma unroll
        for (int mi = 0; mi < 8; ++mi)
            #pragma unroll
            for (int p = 0; p < 4; ++p) acc[mi][p] = bp[p];
    }

    for (int kt = 0; kt < 16; ++kt) {
        __syncthreads();
        #pragma unroll
        for (int i = 0; i < 2; ++i) {
            int f = tid * 2 + i, m = f >> 2, kq = f & 3;
            float4 v = *(const float4*)(g_h1 + ((size_t)(mblk + m)) * 256
                                        + kt * 16 + kq * 4);
            float2* dst = As2 + (kq * 4) * 128 + m;
            dst[0]   = make_float2(v.x, v.x);
            dst[128] = make_float2(v.y, v.y);
            dst[256] = make_float2(v.z, v.z);
            dst[384] = make_float2(v.w, v.w);
            float4 u = *(const float4*)(Wih + ((size_t)(gblk + m)) * 256
                                        + kt * 16 + kq * 4);
            float* bd = Bs + (kq * 4) * 128 + m;
            bd[0] = u.x; bd[128] = u.y; bd[256] = u.z; bd[384] = u.w;
        }
        __syncthreads();
        #pragma unroll
        for (int k = 0; k < 16; ++k) {
            ulonglong2 b01 = *(const ulonglong2*)(Bs + k * 128 + n0);
            ulonglong2 b23 = *(const ulonglong2*)(Bs + k * 128 + n0 + 4);
            const ull* ap = (const ull*)As2 + k * 128 + m0;
            #pragma unroll
            for (int mi = 0; mi < 8; ++mi) {
                ull av = ap[mi];
                acc[mi][0] = fma2(av, b01.x, acc[mi][0]);
                acc[mi][1] = fma2(av, b01.y, acc[mi][1]);
                acc[mi][2] = fma2(av, b23.x, acc[mi][2]);
                acc[mi][3] = fma2(av, b23.y, acc[mi][3]);
            }
        }
    }
    #pragma unroll
    for (int mi = 0; mi < 8; ++mi) {
        float* op = g_xw + (size_t)(mblk + m0 + mi) * 1024 + gblk + n0;
        float2 u0 = unpk(acc[mi][0]), u1 = unpk(acc[mi][1]);
        float2 u2 = unpk(acc[mi][2]), u3 = unpk(acc[mi][3]);
        *(float4*)(op)     = make_float4(u0.x, u0.y, u1.x, u1.y);
        *(float4*)(op + 4) = make_float4(u2.x, u2.y, u3.x, u3.y);
    }
}

// =========================== head ========================================
#define HD_SMEM_F (256*20 + 64*256)
__global__ void head_kernel(const float* __restrict__ Whead,
                            const float* __restrict__ bhead,
                            float* __restrict__ out)
{
    extern __shared__ float sm[];
    float* Wt = sm;
    float* A  = Wt + 256 * 20;
    const int tid = threadIdx.x;
    const int t0  = blockIdx.x * 64;
    const int b   = blockIdx.y;

    for (int idx = tid; idx < 256 * 20; idx += 256) {
        int k = idx / 20, o = idx % 20;
        Wt[idx] = Whead[o * Hn + k];
    }
    for (int idx = tid; idx < 64 * 256; idx += 256) {
        int tt = idx >> 8, k = idx & 255;
        float v = g_h2[((size_t)(t0 + tt) * Bn + b) * Hn + k];
        A[idx] = v >= 0.f ? v : 0.01f * v;
    }
    __syncthreads();

    for (int idx = tid; idx < 64 * 20; idx += 256) {
        int tt = idx / 20, o = idx % 20;
        float acc = bhead[o];
        const float* a = A + tt * 256;
        #pragma unroll 8
        for (int k = 0; k < 256; ++k)
            acc += a[k] * Wt[k * 20 + o];
        out[(size_t)b * OUTC * Tn + (size_t)o * Tn + t0 + tt] = acc;
    }
}

// =========================== launch ======================================
extern "C" void kernel_launch(void* const* d_in, const int* in_sizes, int n_in,
                              void* d_out, int out_size) {
    const float* x     = (const float*)d_in[0];
    const float* Wih0  = (const float*)d_in[1];
    const float* Whh0  = (const float*)d_in[2];
    const float* bih0  = (const float*)d_in[3];
    const float* bhh0  = (const float*)d_in[4];
    const float* Wih1  = (const float*)d_in[5];
    const float* Whh1  = (const float*)d_in[6];
    const float* bih1  = (const float*)d_in[7];
    const float* bhh1  = (const float*)d_in[8];
    const float* Whead = (const float*)d_in[9];
    const float* bhead = (const float*)d_in[10];
    float* out = (float*)d_out;

    const size_t sh = (size_t)HD_SMEM_F * sizeof(float);
    cudaFuncSetAttribute(head_kernel,
                         cudaFuncAttributeMaxDynamicSharedMemorySize, (int)sh);
    cudaFuncSetAttribute(lstm_recur,
                         cudaFuncAttributeMaxDynamicSharedMemorySize, RC_SMEM);

    pre1_gemm<<<dim3(Tn / 16, Bn / 4), 256>>>(x, Wih0, bih0, bhh0);
    lstm_recur<<<128, 256, RC_SMEM>>>(Whh0, 0);
    pre2_gemm<<<dim3((Tn * Bn) / 128, 1024 / 128), 256>>>(Wih1, bih1, bhh1);
    lstm_recur<<<128, 256, RC_SMEM>>>(Whh1, 1);
    head_kernel<<<dim3(Tn / 64, Bn), 256, sh>>>(Whead, bhead, out);
}

// round 8
// speedup vs baseline: 1.0017x; 1.0017x over previous
#include <cuda_runtime.h>
#include <cstdint>

#define Tn   4096
#define Bn   64
#define Hn   256
#define INC  16
#define OUTC 20

typedef unsigned long long ull;

// ---------------- scratch (device globals; no allocations) ---------------
__device__ float g_h1[(size_t)Tn * Bn * Hn];        // 256 MB
__device__ float g_h2[(size_t)Tn * Bn * Hn];        // 256 MB
__device__ float g_xw[(size_t)Tn * Bn * 4 * Hn];    // 1 GB (reused per layer)

// ---------------- helpers ------------------------------------------------
__device__ __forceinline__ ull fma2(ull a, ull b, ull c) {
    ull d; asm("fma.rn.f32x2 %0, %1, %2, %3;" : "=l"(d) : "l"(a), "l"(b), "l"(c));
    return d;
}
__device__ __forceinline__ ull add2(ull a, ull b) {
    ull d; asm("add.rn.f32x2 %0, %1, %2;" : "=l"(d) : "l"(a), "l"(b));
    return d;
}
__device__ __forceinline__ ull pk2(float lo, float hi) {
    ull r; asm("mov.b64 %0, {%1, %2};" : "=l"(r) : "f"(lo), "f"(hi)); return r;
}
__device__ __forceinline__ ull dup2(float v) {
    ull r; asm("mov.b64 %0, {%1, %1};" : "=l"(r) : "f"(v)); return r;
}
__device__ __forceinline__ float2 unpk(ull v) {
    float2 f; asm("mov.b64 {%0, %1}, %2;" : "=f"(f.x), "=f"(f.y) : "l"(v));
    return f;
}
__device__ __forceinline__ uint32_t s2u(const void* p) {
    uint32_t a;
    asm("{ .reg .u64 t; cvta.to.shared.u64 t, %1; cvt.u32.u64 %0, t; }"
        : "=r"(a) : "l"(p));
    return a;
}
__device__ __forceinline__ uint32_t ctarank() {
    uint32_t r; asm("mov.u32 %0, %%cluster_ctarank;" : "=r"(r)); return r;
}
__device__ __forceinline__ void cluster_sync_() {
    asm volatile("barrier.cluster.arrive.aligned;" ::: "memory");
    asm volatile("barrier.cluster.wait.aligned;" ::: "memory");
}
__device__ __forceinline__ void st_async64(uint32_t raddr, uint32_t rmbar,
                                           ull v) {
    asm volatile(
        "st.async.shared::cluster.mbarrier::complete_tx::bytes.b64 [%0], %1, [%2];"
        :: "r"(raddr), "l"(v), "r"(rmbar) : "memory");
}
__device__ __forceinline__ void mbar_init(uint32_t mbar, uint32_t cnt) {
    asm volatile("mbarrier.init.shared.b64 [%0], %1;" :: "r"(mbar), "r"(cnt)
                 : "memory");
}
__device__ __forceinline__ void mbar_expect(uint32_t mbar, uint32_t bytes) {
    asm volatile("mbarrier.arrive.expect_tx.shared.b64 _, [%0], %1;"
                 :: "r"(mbar), "r"(bytes) : "memory");
}
__device__ __forceinline__ void mbar_wait(uint32_t mbar, int phase) {
    asm volatile(
        "{\n\t.reg .pred P;\n"
        "W%=:\n\t"
        "mbarrier.try_wait.parity.acquire.cta.shared::cta.b64 P, [%0], %1, 0x989680;\n\t"
        "@P bra D%=;\n\t"
        "bra W%=;\n"
        "D%=:\n\t}"
        :: "r"(mbar), "r"(phase) : "memory");
}
__device__ __forceinline__ float sigm(float x) {
    return __fdividef(1.f, 1.f + __expf(-x));
}
__device__ __forceinline__ float tanh_fast(float x) {
    float ax = fabsf(x);
    float e  = __expf(ax + ax);
    float t  = 1.f - __fdividef(2.f, e + 1.f);
    return copysignf(t, x);
}

// =========================== recurrent kernel ============================
// grid 128, cluster 8, 256 threads. Cluster cid owns batches [cid*4,+4);
// CTA rank r owns hidden units [r*32,+32); local gate cols c = q*32 + j.
// Dynamic SMEM bytes:
//   buf    [3][4][256] f32 @     0 (12288 B)  h triple buffer
//   mbar   [3] u64         @ 12288 (24 B, pad to 32)
//   part   [8][4][128] ull @ 12320 (32768 B)  k-split partials
//   hstage [4][32]  f32    @ 45088 (512 B)
#define RC_SMEM 45600

__global__ void __launch_bounds__(256, 1) __cluster_dims__(8, 1, 1)
lstm_recur(const float* __restrict__ Whh, int layer)
{
    extern __shared__ __align__(16) char smraw[];
    float* buf    = (float*)smraw;
    ull*   part   = (ull*)(smraw + 12320);
    float* hstage = (float*)(smraw + 45088);
    float* hout   = layer ? g_h2 : g_h1;
    const float* xw = g_xw;

    const int tid  = threadIdx.x;
    const int rank = (int)ctarank();
    const int cid  = blockIdx.x >> 3;
    const int b0   = cid * 4;
    const int j0   = rank * 32;
    const int cq   = tid & 31, ks = tid >> 5;
    const int c0   = cq * 4,   k0 = ks * 32;

    // ---- weights: 4 cols x 32 k, packed over k pairs (registers) ----
    ull w[4][16];
    #pragma unroll
    for (int ci = 0; ci < 4; ++ci) {
        int c  = c0 + ci;
        int gr = ((c >> 5) << 8) + j0 + (c & 31);
        const float4* wp = (const float4*)(Whh + (size_t)gr * Hn + k0);
        #pragma unroll
        for (int q = 0; q < 8; ++q) {
            float4 v = wp[q];
            w[ci][2*q]   = pk2(v.x, v.y);
            w[ci][2*q+1] = pk2(v.z, v.w);
        }
    }

    const uint32_t sbase = s2u(smraw);
    const uint32_t mbar0 = sbase + 12288;

    for (int i = tid; i < 1024; i += 256) buf[i] = 0.f;   // h(0)=0 in buf 0
    if (tid == 0) {
        mbar_init(mbar0,      1);
        mbar_init(mbar0 + 8,  1);
        mbar_init(mbar0 + 16, 1);
    }
    __syncthreads();
    cluster_sync_();          // mbars + buf0 visible cluster-wide

    uint32_t rbase[8];
    #pragma unroll
    for (int r = 0; r < 8; ++r)
        asm("mapa.shared::cluster.u32 %0, %1, %2;"
            : "=r"(rbase[r]) : "r"(sbase), "r"(r));

    // fan-out constants: thread sends pair p to ranks (tid>>6) and (tid>>6)+4
    const int fp   = tid & 63;                 // pair id: b = fp>>4, jp = fp&15
    const int fr   = tid >> 6;
    const uint32_t foff_base =
        (uint32_t)((fp >> 4) * 256 + j0 + 2 * (fp & 15)) * 4u;

    float creg = 0.f;
    int p0 = 0, p1 = 0, p2 = 0;
    int cur = 0;

    for (int t = 0; t < Tn; ++t) {
        const int nxt = (cur == 2) ? 0 : cur + 1;

        // ---- xw prefetch (before wait; DRAM latency hidden) ----
        float x0, x1, x2, x3;
        if (tid < 128) {
            const float* xp = xw + ((size_t)t * Bn + b0 + ks) * 1024 + j0 + cq;
            x0 = xp[0]; x1 = xp[256]; x2 = xp[512]; x3 = xp[768];
        }

        // ---- wait for h(t) ----
        if (t > 0) {
            int ph = (cur == 0) ? p0 : ((cur == 1) ? p1 : p2);
            mbar_wait(mbar0 + cur * 8, ph);
            if (cur == 0) p0 ^= 1; else if (cur == 1) p1 ^= 1; else p2 ^= 1;
        }
        if (tid == 0 && t < Tn - 1) mbar_expect(mbar0 + nxt * 8, 4096);

        // ---- gate partials: 4 cols x 4 batches x 32 k (k-pair packed) ----
        ull acc[4][4];
        #pragma unroll
        for (int ci = 0; ci < 4; ++ci)
            #pragma unroll
            for (int b = 0; b < 4; ++b) acc[ci][b] = 0;
        {
            const ull* hb = (const ull*)buf + cur * 512 + (k0 >> 1);
            #pragma unroll
            for (int b = 0; b < 4; ++b) {
                const ull* hp = hb + b * 128;
                #pragma unroll
                for (int q = 0; q < 16; ++q) {
                    ull h2 = hp[q];
                    acc[0][b] = fma2(h2, w[0][q], acc[0][b]);
                    acc[1][b] = fma2(h2, w[1][q], acc[1][b]);
                    acc[2][b] = fma2(h2, w[2][q], acc[2][b]);
                    acc[3][b] = fma2(h2, w[3][q], acc[3][b]);
                }
            }
        }
        {
            ull* pp = part + (size_t)(ks * 4) * 128 + c0;
            #pragma unroll
            for (int b = 0; b < 4; ++b) {
                ulonglong2 v0; v0.x = acc[0][b]; v0.y = acc[1][b];
                ulonglong2 v1; v1.x = acc[2][b]; v1.y = acc[3][b];
                *(ulonglong2*)(pp + b * 128)     = v0;
                *(ulonglong2*)(pp + b * 128 + 2) = v1;
            }
        }
        __syncthreads();

        // ---- merged reduce + activate (128 threads) ----
        if (tid < 128) {
            const int b = ks, j = cq;          // b = tid>>5 (0..3), j = tid&31
            const ull* pb = part + b * 128 + j;
            ull s0 = pb[0], s1 = pb[32], s2 = pb[64], s3 = pb[96];
            #pragma unroll
            for (int q = 1; q < 8; ++q) {
                const ull* pq = pb + q * 512;
                s0 = add2(s0, pq[0]);
                s1 = add2(s1, pq[32]);
                s2 = add2(s2, pq[64]);
                s3 = add2(s3, pq[96]);
            }
            float2 u0 = unpk(s0), u1 = unpk(s1), u2 = unpk(s2), u3 = unpk(s3);
            float ii = sigm(u0.x + u0.y + x0);
            float ff = sigm(u1.x + u1.y + x1);
            float gg = tanh_fast(u2.x + u2.y + x2);
            float oo = sigm(u3.x + u3.y + x3);
            creg = ff * creg + ii * gg;
            float h = oo * tanh_fast(creg);
            hout[((size_t)t * Bn + b0 + b) * Hn + j0 + j] = h;
            hstage[b * 32 + j] = h;
        }
        __syncthreads();

        // ---- fan-out: 512 b64 sends spread over all 256 threads ----
        if (t < Tn - 1) {
            ull hv = ((const ull*)hstage)[fp];
            uint32_t off  = (uint32_t)(nxt * 4096) + foff_base;
            uint32_t moff = 12288u + (uint32_t)nxt * 8u;
            st_async64(rbase[fr]     + off, rbase[fr]     + moff, hv);
            st_async64(rbase[fr + 4] + off, rbase[fr + 4] + moff, hv);
        }
        cur = nxt;
    }
    cluster_sync_();
}

// =========================== pre1: xw = x*Wih0^T + b =====================
__global__ void __launch_bounds__(256, 2)
pre1_gemm(const float* __restrict__ x, const float* __restrict__ Wih,
          const float* __restrict__ bih, const float* __restrict__ bhh)
{
    __shared__ float xs[64 * 16];
    const int tid = threadIdx.x;
    const int t0  = blockIdx.x * 16;
    const int b0  = blockIdx.y * 4;
    const int g0  = tid * 4;

    ull w[16][2];
    {
        const float4* w0 = (const float4*)(Wih + (size_t)(g0 + 0) * INC);
        const float4* w1 = (const float4*)(Wih + (size_t)(g0 + 1) * INC);
        const float4* w2 = (const float4*)(Wih + (size_t)(g0 + 2) * INC);
        const float4* w3 = (const float4*)(Wih + (size_t)(g0 + 3) * INC);
        #pragma unroll
        for (int dq = 0; dq < 4; ++dq) {
            float4 A = w0[dq], B = w1[dq], C = w2[dq], D = w3[dq];
            w[dq*4+0][0] = pk2(A.x, B.x);  w[dq*4+0][1] = pk2(C.x, D.x);
            w[dq*4+1][0] = pk2(A.y, B.y);  w[dq*4+1][1] = pk2(C.y, D.y);
            w[dq*4+2][0] = pk2(A.z, B.z);  w[dq*4+2][1] = pk2(C.z, D.z);
            w[dq*4+3][0] = pk2(A.w, B.w);  w[dq*4+3][1] = pk2(C.w, D.w);
        }
    }
    ull bp0 = pk2(bih[g0+0] + bhh[g0+0], bih[g0+1] + bhh[g0+1]);
    ull bp1 = pk2(bih[g0+2] + bhh[g0+2], bih[g0+3] + bhh[g0+3]);

    for (int idx = tid; idx < 1024; idx += 256) {
        int row = idx >> 4, d = idx & 15;
        int tt = row >> 2, bb = row & 3;
        xs[idx] = x[(size_t)(b0 + bb) * INC * Tn + (size_t)d * Tn + t0 + tt];
    }
    __syncthreads();

    for (int row = 0; row < 64; ++row) {
        ull a0 = bp0, a1 = bp1;
        const float* xr = xs + row * 16;
        #pragma unroll
        for (int d = 0; d < 16; ++d) {
            ull xd = dup2(xr[d]);
            a0 = fma2(xd, w[d][0], a0);
            a1 = fma2(xd, w[d][1], a1);
        }
        int tt = row >> 2, bb = row & 3;
        size_t m = (size_t)(t0 + tt) * Bn + b0 + bb;
        float2 u0 = unpk(a0), u1 = unpk(a1);
        *(float4*)(g_xw + m * 1024 + g0) = make_float4(u0.x, u0.y, u1.x, u1.y);
    }
}

// =========================== pre2: xw = h1*Wih1^T + b ====================
__global__ void __launch_bounds__(256, 2)
pre2_gemm(const float* __restrict__ Wih,
          const float* __restrict__ bih, const float* __restrict__ bhh)
{
    __shared__ __align__(16) float2 As2[16 * 128];
    __shared__ __align__(16) float  Bs[16 * 128];
    const int tid  = threadIdx.x;
    const int mblk = blockIdx.x * 128;
    const int gblk = blockIdx.y * 128;
    const int tm = tid >> 4, tn = tid & 15;
    const int m0 = tm * 8,   n0 = tn * 8;

    ull acc[8][4];
    {
        ull bp[4];
        #pragma unroll
        for (int p = 0; p < 4; ++p) {
            int g = gblk + n0 + 2 * p;
            bp[p] = pk2(bih[g] + bhh[g], bih[g+1] + bhh[g+1]);
        }
        #pragma unroll
        for (int mi = 0; mi < 8; ++mi)
            #pragma unroll
            for (int p = 0; p < 4; ++p) acc[mi][p] = bp[p];
    }

    for (int kt = 0; kt < 16; ++kt) {
        __syncthreads();
        #pragma unroll
        for (int i = 0; i < 2; ++i) {
            int f = tid * 2 + i, m = f >> 2, kq = f & 3;
            float4 v = *(const float4*)(g_h1 + ((size_t)(mblk + m)) * 256
                                        + kt * 16 + kq * 4);
            float2* dst = As2 + (kq * 4) * 128 + m;
            dst[0]   = make_float2(v.x, v.x);
            dst[128] = make_float2(v.y, v.y);
            dst[256] = make_float2(v.z, v.z);
            dst[384] = make_float2(v.w, v.w);
            float4 u = *(const float4*)(Wih + ((size_t)(gblk + m)) * 256
                                        + kt * 16 + kq * 4);
            float* bd = Bs + (kq * 4) * 128 + m;
            bd[0] = u.x; bd[128] = u.y; bd[256] = u.z; bd[384] = u.w;
        }
        __syncthreads();
        #pragma unroll
        for (int k = 0; k < 16; ++k) {
            ulonglong2 b01 = *(const ulonglong2*)(Bs + k * 128 + n0);
            ulonglong2 b23 = *(const ulonglong2*)(Bs + k * 128 + n0 + 4);
            const ull* ap = (const ull*)As2 + k * 128 + m0;
            #pragma unroll
            for (int mi = 0; mi < 8; ++mi) {
                ull av = ap[mi];
                acc[mi][0] = fma2(av, b01.x, acc[mi][0]);
                acc[mi][1] = fma2(av, b01.y, acc[mi][1]);
                acc[mi][2] = fma2(av, b23.x, acc[mi][2]);
                acc[mi][3] = fma2(av, b23.y, acc[mi][3]);
            }
        }
    }
    #pragma unroll
    for (int mi = 0; mi < 8; ++mi) {
        float* op = g_xw + (size_t)(mblk + m0 + mi) * 1024 + gblk + n0;
        float2 u0 = unpk(acc[mi][0]), u1 = unpk(acc[mi][1]);
        float2 u2 = unpk(acc[mi][2]), u3 = unpk(acc[mi][3]);
        *(float4*)(op)     = make_float4(u0.x, u0.y, u1.x, u1.y);
        *(float4*)(op + 4) = make_float4(u2.x, u2.y, u3.x, u3.y);
    }
}

// =========================== head ========================================
#define HD_SMEM_F (256*20 + 64*256)
__global__ void head_kernel(const float* __restrict__ Whead,
                            const float* __restrict__ bhead,
                            float* __restrict__ out)
{
    extern __shared__ float sm[];
    float* Wt = sm;
    float* A  = Wt + 256 * 20;
    const int tid = threadIdx.x;
    const int t0  = blockIdx.x * 64;
    const int b   = blockIdx.y;

    for (int idx = tid; idx < 256 * 20; idx += 256) {
        int k = idx / 20, o = idx % 20;
        Wt[idx] = Whead[o * Hn + k];
    }
    for (int idx = tid; idx < 64 * 256; idx += 256) {
        int tt = idx >> 8, k = idx & 255;
        float v = g_h2[((size_t)(t0 + tt) * Bn + b) * Hn + k];
        A[idx] = v >= 0.f ? v : 0.01f * v;
    }
    __syncthreads();

    for (int idx = tid; idx < 64 * 20; idx += 256) {
        int tt = idx / 20, o = idx % 20;
        float acc = bhead[o];
        const float* a = A + tt * 256;
        #pragma unroll 8
        for (int k = 0; k < 256; ++k)
            acc += a[k] * Wt[k * 20 + o];
        out[(size_t)b * OUTC * Tn + (size_t)o * Tn + t0 + tt] = acc;
    }
}

// =========================== launch ======================================
extern "C" void kernel_launch(void* const* d_in, const int* in_sizes, int n_in,
                              void* d_out, int out_size) {
    const float* x     = (const float*)d_in[0];
    const float* Wih0  = (const float*)d_in[1];
    const float* Whh0  = (const float*)d_in[2];
    const float* bih0  = (const float*)d_in[3];
    const float* bhh0  = (const float*)d_in[4];
    const float* Wih1  = (const float*)d_in[5];
    const float* Whh1  = (const float*)d_in[6];
    const float* bih1  = (const float*)d_in[7];
    const float* bhh1  = (const float*)d_in[8];
    const float* Whead = (const float*)d_in[9];
    const float* bhead = (const float*)d_in[10];
    float* out = (float*)d_out;

    const size_t sh = (size_t)HD_SMEM_F * sizeof(float);
    cudaFuncSetAttribute(head_kernel,
                         cudaFuncAttributeMaxDynamicSharedMemorySize, (int)sh);
    cudaFuncSetAttribute(lstm_recur,
                         cudaFuncAttributeMaxDynamicSharedMemorySize, RC_SMEM);

    pre1_gemm<<<dim3(Tn / 16, Bn / 4), 256>>>(x, Wih0, bih0, bhh0);
    lstm_recur<<<128, 256, RC_SMEM>>>(Whh0, 0);
    pre2_gemm<<<dim3((Tn * Bn) / 128, 1024 / 128), 256>>>(Wih1, bih1, bhh1);
    lstm_recur<<<128, 256, RC_SMEM>>>(Whh1, 1);
    head_kernel<<<dim3(Tn / 64, Bn), 256, sh>>>(Whead, bhead, out);
}